// round 7
// baseline (speedup 1.0000x reference)
#include <cuda_runtime.h>

#define NANCH 2048
#define NCLS 21
#define MAXOUT 200
#define NMS_THR 0.5f
#define SCORE_THR 0.5f
#define CAND_CAP (NCLS * MAXOUT)   /* 4200 */
#define FULLMASK 0xFFFFFFFFu
#define SEG 256
#define NBUCK 2048

typedef unsigned long long ull;

// Scratch (no allocations allowed)
__device__ float g_scoreT[NCLS * NANCH];
__device__ ull   g_cand[CAND_CAP];
__device__ float g_cand_box[CAND_CAP * 4];
__device__ int   g_cnt[NCLS];
__device__ ull   g_best[NCLS];
__device__ float g_best_box[NCLS * 4];

// dynamic smem layout for class_nms
#define OFF_BBOX 0        /* float4[2048]  32768 */
#define OFF_SKEY 32768    /* ull[2048]     16384 */
#define OFF_AREA 49152    /* float[2048]    8192 */
#define OFF_BCNT 57344    /* int[2048]      8192 */
#define OFF_BASE 65536    /* int[2048]      8192 */
#define OFF_SEGM 73728    /* uint[256*8]    8192 */
#define OFF_KEPT 81920    /* int[256]       1024 */
#define CSMEM    82944

// ---------------------------------------------------------------------------
// Kernel 0: per-anchor argmax mask + transposed score write (done ONCE).
// ---------------------------------------------------------------------------
__global__ __launch_bounds__(256)
void score_kernel(const float* __restrict__ probs)
{
    __shared__ float sp[256 * NCLS];
    const int t = threadIdx.x;
    const int base = blockIdx.x * 256;

    const float* src = probs + base * NCLS;
    #pragma unroll
    for (int i = t; i < 256 * NCLS; i += 256) sp[i] = src[i];
    __syncthreads();

    const float* pr = sp + t * NCLS;
    float p0 = pr[0];
    float m = pr[1];
    #pragma unroll
    for (int k = 2; k < NCLS; k++) m = fmaxf(m, pr[k]);
    bool valid = (m > p0);

    int n = base + t;
    #pragma unroll
    for (int c = 0; c < NCLS; c++)
        g_scoreT[c * NANCH + n] = valid ? pr[c] : 0.0f;
}

__device__ __forceinline__ float4 dec_box(const float* __restrict__ rois,
                                          const float* __restrict__ deltas,
                                          int c, int n)
{
    float4 rb = ((const float4*)rois)[n];
    const float* dd = deltas + n * (NCLS * 4) + c * 4;
    float dy = dd[0] * 0.1f;
    float dx = dd[1] * 0.1f;
    float dh = dd[2] * 0.2f;
    float dw = dd[3] * 0.2f;
    float h  = rb.z - rb.x;
    float w  = rb.w - rb.y;
    float cy = rb.x + 0.5f * h;
    float cx = rb.y + 0.5f * w;
    float nh = __expf(dh) * h;
    float nw = __expf(dw) * w;
    float ncy = dy * h + cy;
    float ncx = dx * w + cx;
    return make_float4(ncy - 0.5f * nh, ncx - 0.5f * nw,
                       ncy + 0.5f * nh, ncx + 0.5f * nw);
}

// ---------------------------------------------------------------------------
// Kernel 1: one block per class, 1024 threads.
// Bucket sort (O(N), ~6 barriers) + segment-256 mask-matrix NMS.
// ---------------------------------------------------------------------------
__global__ __launch_bounds__(1024, 1)
void class_nms_kernel(const float* __restrict__ rois,
                      const float* __restrict__ deltas)
{
    extern __shared__ __align__(16) unsigned char dsm[];
    float4*   bbox    = (float4*)(dsm + OFF_BBOX);
    ull*      skey    = (ull*)(dsm + OFF_SKEY);
    float*    barea   = (float*)(dsm + OFF_AREA);
    int*      bcnt    = (int*)(dsm + OFF_BCNT);
    int*      bbase   = (int*)(dsm + OFF_BASE);
    unsigned* segmat  = (unsigned*)(dsm + OFF_SEGM);
    int*      keptlist= (int*)(dsm + OFF_KEPT);

    __shared__ unsigned rem[64];
    __shared__ unsigned ballots[64];
    __shared__ int wpre[64];
    __shared__ int wtmp[32];
    __shared__ int wexcl[32];
    __shared__ ull maxw[32];
    __shared__ int s_P, s_cnt, s_kin, s_done, s_istop;

    const int c = blockIdx.x;
    const int t = threadIdx.x;
    const int lane = t & 31;
    const int warp = t >> 5;

    // ---- init + zero bucket counts ------------------------------------------
    bcnt[t] = 0;
    bcnt[t + 1024] = 0;
    if (t < 64) rem[t] = 0;
    if (t == 0) { s_cnt = 0; s_done = 0; s_istop = NANCH; }
    __syncthreads();

    // ---- keys, flags, bucket slots, block max -------------------------------
    const float* scT = g_scoreT + c * NANCH;
    float sA = scT[t];
    float sB = scT[t + 1024];
    ull keyA = ((ull)__float_as_uint(sA) << 32) | (unsigned)(NANCH - 1 - t);
    ull keyB = ((ull)__float_as_uint(sB) << 32) | (unsigned)(NANCH - 1 - (t + 1024));
    int bA = -1, bB = -1, slA = 0, slB = 0;
    if (sA > SCORE_THR) {
        bA = min(max((int)((sA - 0.5f) * 4096.0f), 0), NBUCK - 1);
        slA = atomicAdd(&bcnt[bA], 1);
    }
    if (sB > SCORE_THR) {
        bB = min(max((int)((sB - 0.5f) * 4096.0f), 0), NBUCK - 1);
        slB = atomicAdd(&bcnt[bB], 1);
    }
    {   // block max key (for fallback best)
        ull km = keyA > keyB ? keyA : keyB;
        #pragma unroll
        for (int d = 16; d >= 1; d >>= 1) {
            ull o = __shfl_xor_sync(FULLMASK, km, d);
            if (o > km) km = o;
        }
        if (lane == 0) maxw[warp] = km;
    }
    __syncthreads();

    // ---- suffix scan of bucket pair-sums (descending bases) -----------------
    int sp = bcnt[2 * t] + bcnt[2 * t + 1];
    int x = sp;
    #pragma unroll
    for (int d = 1; d < 32; d <<= 1) {
        int o = __shfl_down_sync(FULLMASK, x, d);
        if (lane + d < 32) x += o;
    }
    if (lane == 0) wtmp[warp] = x;
    __syncthreads();

    if (warp == 0) {
        int x2 = wtmp[lane];
        int tot = x2;
        #pragma unroll
        for (int d = 1; d < 32; d <<= 1) {
            int o = __shfl_down_sync(FULLMASK, x2, d);
            if (lane + d < 32) x2 += o;
        }
        wexcl[lane] = x2 - tot;              // suffix over warps > lane
        if (lane == 0) s_P = x2;             // total candidates

        // finish block max; write per-class fallback
        ull km2 = maxw[lane];
        #pragma unroll
        for (int d = 16; d >= 1; d >>= 1) {
            ull o = __shfl_xor_sync(FULLMASK, km2, d);
            if (o > km2) km2 = o;
        }
        if (lane == 0) {
            g_best[c] = ((km2 >> 32) << 32) | (unsigned)(0xFFFFFFFFu - (unsigned)c);
            int nb = NANCH - 1 - (int)(km2 & 0xFFFFFFFFu);
            ((float4*)g_best_box)[c] = dec_box(rois, deltas, c, nb);
        }
    }
    __syncthreads();

    int S = x + wexcl[warp];                 // suffix incl over pairs >= t
    int E = S - sp;                          // suffix over pairs > t
    bbase[2 * t + 1] = E;
    bbase[2 * t]     = E + bcnt[2 * t + 1];
    __syncthreads();

    // ---- scatter into sorted-candidate array --------------------------------
    if (bA >= 0) skey[bbase[bA] + slA] = keyA;
    if (bB >= 0) skey[bbase[bB] + slB] = keyB;
    __syncthreads();

    // ---- exact tie-fix: sort multi-key buckets (full ull key, descending) ---
    #pragma unroll
    for (int r = 0; r < 2; r++) {
        int bb = 2 * t + r;
        int cnt = bcnt[bb];
        if (cnt > 1) {
            int base = bbase[bb];
            for (int a = base + 1; a < base + cnt; a++) {
                ull v = skey[a];
                int b2 = a;
                while (b2 > base && skey[b2 - 1] < v) { skey[b2] = skey[b2 - 1]; b2--; }
                skey[b2] = v;
            }
        }
    }
    __syncthreads();
    const int P = s_P;

    // ---- decode boxes (sorted candidate order) ------------------------------
    #pragma unroll
    for (int rep = 0; rep < 2; rep++) {
        int p = t + rep * 1024;
        if (p < P) {
            ull key = skey[p];
            int n = NANCH - 1 - (int)(key & 0xFFFFFFFFu);
            float4 bx = dec_box(rois, deltas, c, n);
            bbox[p] = bx;
            barea[p] = (bx.z - bx.x) * (bx.w - bx.y);
        }
    }
    __syncthreads();

    // ---- segmented NMS -------------------------------------------------------
    for (int seg = 0; seg < P; seg += SEG) {
        // (a) intra-segment matrix build with dead-column gating
        {
            int w = t >> 7;
            int r0 = (t & 127) * 2;
            int r1 = r0 + 1;
            int i0 = seg + r0;
            int i1 = seg + r1;
            int jbase = seg + w * 32;
            int nb = P - jbase;
            unsigned vm = (nb >= 32) ? 0xFFFFFFFFu : ((nb <= 0) ? 0u : ((1u << nb) - 1u));
            unsigned remj = rem[(unsigned)jbase >> 5];
            unsigned valid = vm & ~remj;              // warp-uniform

            bool a0 = (i0 < P) && !((rem[i0 >> 5] >> (i0 & 31)) & 1);
            bool a1 = (i1 < P) && !((rem[i1 >> 5] >> (i1 & 31)) & 1);

            int d0 = i0 - jbase;
            int d1 = i1 - jbase;
            unsigned gtm0 = (d0 < 0) ? 0xFFFFFFFFu : ((d0 >= 31) ? 0u : (0xFFFFFFFEu << d0));
            unsigned gtm1 = (d1 < 0) ? 0xFFFFFFFFu : ((d1 >= 31) ? 0u : (0xFFFFFFFEu << d1));

            unsigned bits0 = 0, bits1 = 0;
            if ((a0 || a1) && valid) {
                float4 B0 = bbox[a0 ? i0 : (seg)];
                float  A0 = barea[a0 ? i0 : (seg)];
                float4 B1 = bbox[a1 ? i1 : (seg)];
                float  A1 = barea[a1 ? i1 : (seg)];
                unsigned it = valid;
                while (it) {
                    int jl = __ffs(it) - 1;
                    it &= it - 1;
                    int j = jbase + jl;
                    float4 Bj = bbox[j];
                    float  Aj = barea[j];
                    {
                        float ih = fmaxf(fminf(B0.z, Bj.z) - fmaxf(B0.x, Bj.x), 0.0f);
                        float iw = fmaxf(fminf(B0.w, Bj.w) - fmaxf(B0.y, Bj.y), 0.0f);
                        float inter = ih * iw;
                        float iou = inter / (A0 + Aj - inter + 1e-9f);
                        bits0 |= (iou > NMS_THR ? 1u : 0u) << jl;
                    }
                    {
                        float ih = fmaxf(fminf(B1.z, Bj.z) - fmaxf(B1.x, Bj.x), 0.0f);
                        float iw = fmaxf(fminf(B1.w, Bj.w) - fmaxf(B1.y, Bj.y), 0.0f);
                        float inter = ih * iw;
                        float iou = inter / (A1 + Aj - inter + 1e-9f);
                        bits1 |= (iou > NMS_THR ? 1u : 0u) << jl;
                    }
                }
            }
            if (a0) segmat[r0 * 8 + w] = bits0 & gtm0;
            if (a1) segmat[r1 * 8 + w] = bits1 & gtm1;
        }
        __syncthreads();

        // (b) warp-serial greedy scan (warp 0, uniform lanes)
        if (warp == 0) {
            unsigned acc[8];
            int sw = seg >> 5;
            #pragma unroll
            for (int lw = 0; lw < 8; lw++) acc[lw] = rem[sw + lw];
            int cnt = s_cnt;
            int kin = 0;
            bool dn = false;
            int istop = 0;
            for (int lw = 0; lw < 8 && !dn; lw++) {
                int base = seg + lw * 32;
                int nb = P - base;
                if (nb <= 0) break;
                unsigned vm = (nb >= 32) ? 0xFFFFFFFFu : ((1u << nb) - 1u);
                unsigned alive = ~acc[lw] & vm;
                while (alive) {
                    int b = __ffs(alive) - 1;
                    int i = base + b;
                    cnt++;
                    keptlist[kin++] = i;
                    if (cnt >= MAXOUT) { istop = i; dn = true; break; }
                    int r = i - seg;
                    #pragma unroll
                    for (int w2 = 0; w2 < 8; w2++) acc[w2] |= segmat[r * 8 + w2];
                    alive = (~acc[lw]) & vm & (0xFFFFFFFEu << b);
                }
            }
            if (lane == 0) {
                #pragma unroll
                for (int lw = 0; lw < 8; lw++) rem[sw + lw] = acc[lw];
                s_cnt = cnt;
                s_kin = kin;
                if (dn) { s_done = 1; s_istop = istop; }
            }
        }
        __syncthreads();

        if (s_done) break;
        int kin = s_kin;

        // (c) cross suppression: later j vs this segment's kept list
        for (int j = seg + SEG + t; j < P; j += 1024) {
            if ((rem[j >> 5] >> (j & 31)) & 1) continue;
            float4 bj = bbox[j];
            float aj = barea[j];
            for (int k = 0; k < kin; k++) {
                int i = keptlist[k];
                float4 bi = bbox[i];
                float ih = fmaxf(fminf(bi.z, bj.z) - fmaxf(bi.x, bj.x), 0.0f);
                float iw = fmaxf(fminf(bi.w, bj.w) - fmaxf(bi.y, bj.y), 0.0f);
                float inter = ih * iw;
                float iou = inter / (barea[i] + aj - inter + 1e-9f);
                if (iou > NMS_THR) {
                    atomicOr(&rem[j >> 5], 1u << (j & 31));
                    break;
                }
            }
        }
        __syncthreads();
    }
    __syncthreads();
    const int i_stop = s_istop;

    // ---- ballot-scan ranking + candidate emission ----------------------------
    int p1 = t + 1024;
    bool f0 = (t < P)  && (t <= i_stop)  && !((rem[t >> 5] >> (t & 31)) & 1);
    bool f1 = (p1 < P) && (p1 <= i_stop) && !((rem[p1 >> 5] >> (p1 & 31)) & 1);
    unsigned b0 = __ballot_sync(FULLMASK, f0);
    unsigned b1 = __ballot_sync(FULLMASK, f1);
    if (lane == 0) { ballots[warp] = b0; ballots[32 + warp] = b1; }
    __syncthreads();
    if (t < 64) {
        int s = 0;
        for (int u = 0; u < t; u++) s += __popc(ballots[u]);
        wpre[t] = s;
    }
    __syncthreads();

    unsigned lmask = (1u << lane) - 1u;
    if (f0) {
        int rank = wpre[warp] + __popc(b0 & lmask);
        int flatc = c * MAXOUT + rank;
        g_cand[flatc] = ((skey[t] >> 32) << 32) | (unsigned)(0xFFFFFFFFu - (unsigned)flatc);
        ((float4*)g_cand_box)[flatc] = bbox[t];
    }
    if (f1) {
        int rank = wpre[32 + warp] + __popc(b1 & lmask);
        int flatc = c * MAXOUT + rank;
        g_cand[flatc] = ((skey[p1] >> 32) << 32) | (unsigned)(0xFFFFFFFFu - (unsigned)flatc);
        ((float4*)g_cand_box)[flatc] = bbox[p1];
    }
    if (t == 0) {
        int total = 0;
        #pragma unroll
        for (int u = 0; u < 64; u++) total += __popc(ballots[u]);
        g_cnt[c] = total;
    }
}

// ---------------------------------------------------------------------------
// Kernel 2: global top-200 via histogram select + exact ranking (dense keys)
// ---------------------------------------------------------------------------
__global__ __launch_bounds__(1024, 1)
void topk_kernel(float* __restrict__ out)
{
    __shared__ ull subkeys[4224];
    __shared__ ull slots[MAXOUT];
    __shared__ int hist[256];
    __shared__ int scnt_s[NCLS];
    __shared__ int s_m, s_bstar;

    const int t = threadIdx.x;

    if (t < 256) hist[t] = 0;
    if (t < MAXOUT) slots[t] = 0ULL;
    if (t < NCLS) scnt_s[t] = g_cnt[t];
    if (t == 0) { s_m = 0; s_bstar = 0; }
    __syncthreads();

    ull myk[5];
    #pragma unroll
    for (int rep = 0; rep < 5; rep++) {
        int i = t + rep * 1024;
        ull key = 0ULL;
        if (i < CAND_CAP) {
            int c = i / MAXOUT;
            int r = i - c * MAXOUT;
            if (r < scnt_s[c]) key = g_cand[i];
        }
        myk[rep] = key;
        if (key) {
            unsigned sb = (unsigned)(key >> 32);
            int bin = (int)((sb - 0x3F000000u) >> 15);
            bin = min(max(bin, 0), 255);
            atomicAdd(&hist[bin], 1);
        }
    }
    __syncthreads();

    // parallel suffix selection of boundary bin
    if (t < 256) {
        int sum = 0;
        for (int b = t; b < 256; b++) sum += hist[b];
        if (sum >= MAXOUT) atomicMax(&s_bstar, t);
    }
    __syncthreads();
    int bstar = s_bstar;

    // dense compaction of boundary superset
    #pragma unroll
    for (int rep = 0; rep < 5; rep++) {
        ull key = myk[rep];
        if (key) {
            unsigned sb = (unsigned)(key >> 32);
            int bin = (int)((sb - 0x3F000000u) >> 15);
            bin = min(max(bin, 0), 255);
            if (bin >= bstar) {
                int pos = atomicAdd(&s_m, 1);
                subkeys[pos] = key;
            }
        }
    }
    __syncthreads();
    int M = s_m;

    // exact rank within superset (keys unique)
    for (int s = t; s < M; s += 1024) {
        ull k = subkeys[s];
        int r = 0;
        for (int m = 0; m < M; m++)
            r += (subkeys[m] > k) ? 1 : 0;
        if (r < MAXOUT) slots[r] = k;
    }
    __syncthreads();

    if (t < MAXOUT) {
        float b0 = 0.f, b1 = 0.f, b2 = 0.f, b3 = 0.f, lab = 0.f, sc = 0.f;
        ull key = slots[t];
        if (key != 0ULL) {
            sc = __uint_as_float((unsigned)(key >> 32));
            unsigned flatc = 0xFFFFFFFFu - (unsigned)(key & 0xFFFFFFFFu);
            lab = (float)(flatc / MAXOUT);
            float4 bb = ((const float4*)g_cand_box)[flatc];
            b0 = fminf(fmaxf(bb.x, 0.f), 1.f);
            b1 = fminf(fmaxf(bb.y, 0.f), 1.f);
            b2 = fminf(fmaxf(bb.z, 0.f), 1.f);
            b3 = fminf(fmaxf(bb.w, 0.f), 1.f);
        } else if (t == 0 && M == 0) {
            ull best = 0ULL;
            #pragma unroll
            for (int c2 = 0; c2 < NCLS; c2++) {
                ull v = g_best[c2];
                if (v > best) best = v;
            }
            float s = __uint_as_float((unsigned)(best >> 32));
            if (s >= 0.001f) {
                sc = s;
                int c2 = (int)(0xFFFFFFFFu - (unsigned)(best & 0xFFFFFFFFu));
                lab = (float)c2;
                float4 bb = ((const float4*)g_best_box)[c2];
                b0 = fminf(fmaxf(bb.x, 0.f), 1.f);
                b1 = fminf(fmaxf(bb.y, 0.f), 1.f);
                b2 = fminf(fmaxf(bb.z, 0.f), 1.f);
                b3 = fminf(fmaxf(bb.w, 0.f), 1.f);
            }
        }
        out[t * 4 + 0] = b0;
        out[t * 4 + 1] = b1;
        out[t * 4 + 2] = b2;
        out[t * 4 + 3] = b3;
        out[MAXOUT * 4 + t] = lab;
        out[MAXOUT * 5 + t] = sc;
    }
}

extern "C" void kernel_launch(void* const* d_in, const int* in_sizes, int n_in,
                              void* d_out, int out_size)
{
    (void)in_sizes; (void)n_in; (void)out_size;
    const float* rois   = (const float*)d_in[0];
    const float* deltas = (const float*)d_in[1];
    const float* probs  = (const float*)d_in[2];
    float* out = (float*)d_out;

    cudaFuncSetAttribute(class_nms_kernel,
                         cudaFuncAttributeMaxDynamicSharedMemorySize, CSMEM);

    score_kernel<<<NANCH / 256, 256>>>(probs);
    class_nms_kernel<<<NCLS, 1024, CSMEM>>>(rois, deltas);
    topk_kernel<<<1, 1024>>>(out);
}

// round 8
// speedup vs baseline: 1.3879x; 1.3879x over previous
#include <cuda_runtime.h>

#define NANCH 2048
#define NCLS 21
#define MAXOUT 200
#define NMS_THR 0.5f
#define SCORE_THR 0.5f
#define CAND_CAP (NCLS * MAXOUT)   /* 4200 */
#define FULLMASK 0xFFFFFFFFu
#define SEG 256

typedef unsigned long long ull;

// Scratch (no allocations allowed)
__device__ float g_scoreT[NCLS * NANCH];    // transposed masked scores
__device__ ull   g_cand[CAND_CAP];          // per-class rank-ordered candidate keys
__device__ float g_cand_box[CAND_CAP * 4];  // matching boxes
__device__ int   g_cnt[NCLS];
__device__ ull   g_best[NCLS];              // per-class fallback (rank-0 kept)
__device__ float g_best_box[NCLS * 4];

// ---------------------------------------------------------------------------
// Kernel 0: per-anchor argmax mask + transposed score write (done ONCE).
// ---------------------------------------------------------------------------
__global__ __launch_bounds__(256)
void score_kernel(const float* __restrict__ probs)
{
    __shared__ float sp[256 * NCLS];
    const int t = threadIdx.x;
    const int base = blockIdx.x * 256;

    const float* src = probs + base * NCLS;
    #pragma unroll
    for (int i = t; i < 256 * NCLS; i += 256) sp[i] = src[i];
    __syncthreads();

    const float* pr = sp + t * NCLS;
    float p0 = pr[0];
    float m = pr[1];
    #pragma unroll
    for (int k = 2; k < NCLS; k++) m = fmaxf(m, pr[k]);
    bool valid = (m > p0);

    int n = base + t;
    #pragma unroll
    for (int c = 0; c < NCLS; c++)
        g_scoreT[c * NANCH + n] = valid ? pr[c] : 0.0f;
}

__device__ __forceinline__ ull cmpx(ull v, ull o, bool takeMax) {
    return takeMax ? (v > o ? v : o) : (v < o ? v : o);
}

// Register bitonic tail: j=32 (in-thread) then j=16..1 (shfl_xor).
__device__ __forceinline__ void reg_tail(ull& lo, ull& hi, int e_lo, int k, int lane) {
    if (k >= 64) {
        bool desc = ((e_lo & k) == 0);
        if ((lo < hi) == desc) { ull tmp = lo; lo = hi; hi = tmp; }
    }
    #pragma unroll
    for (int j = 16; j >= 1; j >>= 1) {
        if (j > (k >> 1)) continue;
        bool is_low = ((lane & j) == 0);
        {
            ull o = __shfl_xor_sync(FULLMASK, lo, j);
            bool desc = ((e_lo & k) == 0);
            lo = cmpx(lo, o, is_low == desc);
        }
        {
            ull o = __shfl_xor_sync(FULLMASK, hi, j);
            bool desc = (((e_lo + 32) & k) == 0);
            hi = cmpx(hi, o, is_low == desc);
        }
    }
}

// ---------------------------------------------------------------------------
// Kernel 1: one block per class, 1024 threads. Segment-256 mask-matrix NMS.
// (verbatim R6 version — measured 48us)
// ---------------------------------------------------------------------------
__global__ __launch_bounds__(1024, 1)
void class_nms_kernel(const float* __restrict__ rois,
                      const float* __restrict__ deltas)
{
    __shared__ __align__(16) unsigned char sraw[32768];  // keys, then float4 boxes
    __shared__ unsigned segmat[SEG * 8];   // intra-segment suppression rows (8KB)
    __shared__ int keptlist[SEG];
    __shared__ unsigned rem[64];           // removed bitmask over sorted positions
    __shared__ unsigned ballots[64];
    __shared__ int wpre[64];
    __shared__ int s_P, s_cnt, s_kin, s_done, s_istop;

    float4* bbox = (float4*)sraw;          // bbox[p] = (y1,x1,y2,x2), p < P
    ull*    skey = (ull*)sraw;             // overlaps bbox (freed before decode)

    const int c = blockIdx.x;
    const int t = threadIdx.x;
    const int lane = t & 31;
    const int warp = t >> 5;
    const int e_lo = warp * 64 + lane;
    const int e_hi = e_lo + 32;

    // ---- phase 0: coalesced score loads -> keys in registers ---------------
    const float* scT = g_scoreT + c * NANCH;
    ull lo = ((ull)__float_as_uint(scT[e_lo]) << 32) | (unsigned)(NANCH - 1 - e_lo);
    ull hi = ((ull)__float_as_uint(scT[e_hi]) << 32) | (unsigned)(NANCH - 1 - e_hi);

    // ---- phase 1: hybrid bitonic sort (descending) --------------------------
    #pragma unroll
    for (int k = 2; k <= 64; k <<= 1)
        reg_tail(lo, hi, e_lo, k, lane);
    skey[e_lo] = lo; skey[e_hi] = hi;
    __syncthreads();

    for (int k = 128; k <= NANCH; k <<= 1) {
        for (int j = k >> 1; j >= 64; j >>= 1) {
            int idx = ((t & ~(j - 1)) << 1) | (t & (j - 1));
            int pid = idx | j;
            ull a = skey[idx];
            ull b = skey[pid];
            bool desc = ((idx & k) == 0);
            if ((a < b) == desc) { skey[idx] = b; skey[pid] = a; }
            __syncthreads();
        }
        lo = skey[e_lo]; hi = skey[e_hi];
        reg_tail(lo, hi, e_lo, k, lane);
        skey[e_lo] = lo; skey[e_hi] = hi;
        __syncthreads();
    }

    ull k0 = skey[t];
    ull k1 = skey[t + 1024];
    if (t < 64) rem[t] = 0;
    if (t == 0) { s_P = 0; s_cnt = 0; s_done = 0; s_istop = NANCH; }
    __syncthreads();                       // key reads + inits complete

    float sc0 = __uint_as_float((unsigned)(k0 >> 32));
    float sc1 = __uint_as_float((unsigned)(k1 >> 32));

    // candidate-prefix length P = #scores > 0.5 (prefix of sorted order)
    {
        unsigned c0 = __ballot_sync(FULLMASK, sc0 > SCORE_THR);
        unsigned c1 = __ballot_sync(FULLMASK, sc1 > SCORE_THR);
        if (lane == 0) atomicAdd(&s_P, __popc(c0) + __popc(c1));
    }
    __syncthreads();
    const int P = s_P;

    // ---- phase 2: decode boxes (sorted order, prefix only) ------------------
    #pragma unroll
    for (int rep = 0; rep < 2; rep++) {
        int p = t + rep * 1024;
        if (p < P || p == 0) {
            ull key = rep ? k1 : k0;
            int n = NANCH - 1 - (int)(key & 0xFFFFFFFFu);
            float4 rb = ((const float4*)rois)[n];
            const float* dd = deltas + n * (NCLS * 4) + c * 4;
            float dy = dd[0] * 0.1f;
            float dx = dd[1] * 0.1f;
            float dh = dd[2] * 0.2f;
            float dw = dd[3] * 0.2f;
            float h  = rb.z - rb.x;
            float w  = rb.w - rb.y;
            float cy = rb.x + 0.5f * h;
            float cx = rb.y + 0.5f * w;
            float nh = __expf(dh) * h;
            float nw = __expf(dw) * w;
            float ncy = dy * h + cy;
            float ncx = dx * w + cx;
            bbox[p] = make_float4(ncy - 0.5f * nh, ncx - 0.5f * nw,
                                  ncy + 0.5f * nh, ncx + 0.5f * nw);
        }
    }
    __syncthreads();

    // ---- phase 3: segmented NMS ---------------------------------------------
    for (int seg = 0; seg < P; seg += SEG) {
        // (a) intra-segment matrix build.
        {
            int w = t >> 7;
            int r0 = (t & 127) * 2;
            int r1 = r0 + 1;
            int i0 = seg + r0;
            int i1 = seg + r1;
            int jbase = seg + w * 32;
            int nb = P - jbase;
            unsigned vm = (nb >= 32) ? 0xFFFFFFFFu : ((nb <= 0) ? 0u : ((1u << nb) - 1u));
            int rw0 = r0 >> 5, rw1 = r1 >> 5;
            unsigned m0 = (w > rw0) ? vm : ((w < rw0) ? 0u : ((0xFFFFFFFEu << (r0 & 31)) & vm));
            unsigned m1 = (w > rw1) ? vm : ((w < rw1) ? 0u : ((0xFFFFFFFEu << (r1 & 31)) & vm));
            if (i0 >= P || ((rem[i0 >> 5] >> (i0 & 31)) & 1)) m0 = 0;
            if (i1 >= P || ((rem[i1 >> 5] >> (i1 & 31)) & 1)) m1 = 0;
            if (m0 | m1) {
                float4 b0 = bbox[i0 < P ? i0 : 0];
                float4 b1 = bbox[i1 < P ? i1 : 0];
                float a0 = (b0.z - b0.x) * (b0.w - b0.y);
                float a1 = (b1.z - b1.x) * (b1.w - b1.y);
                unsigned bits0 = 0, bits1 = 0;
                for (int jl = 0; jl < 32; jl++) {
                    float4 bj = bbox[jbase + jl < P ? jbase + jl : 0];
                    float aj = (bj.z - bj.x) * (bj.w - bj.y);
                    {
                        float ih = fmaxf(fminf(b0.z, bj.z) - fmaxf(b0.x, bj.x), 0.0f);
                        float iw = fmaxf(fminf(b0.w, bj.w) - fmaxf(b0.y, bj.y), 0.0f);
                        float inter = ih * iw;
                        float iou = inter / (a0 + aj - inter + 1e-9f);
                        bits0 |= (iou > NMS_THR ? 1u : 0u) << jl;
                    }
                    {
                        float ih = fmaxf(fminf(b1.z, bj.z) - fmaxf(b1.x, bj.x), 0.0f);
                        float iw = fmaxf(fminf(b1.w, bj.w) - fmaxf(b1.y, bj.y), 0.0f);
                        float inter = ih * iw;
                        float iou = inter / (a1 + aj - inter + 1e-9f);
                        bits1 |= (iou > NMS_THR ? 1u : 0u) << jl;
                    }
                }
                segmat[r0 * 8 + w] = bits0 & m0;
                segmat[r1 * 8 + w] = bits1 & m1;
            } else {
                segmat[r0 * 8 + w] = 0;
                segmat[r1 * 8 + w] = 0;
            }
        }
        __syncthreads();

        // (b) warp-serial greedy scan of this segment (warp 0, uniform lanes)
        if (warp == 0) {
            unsigned acc[8];
            int sw = seg >> 5;
            #pragma unroll
            for (int lw = 0; lw < 8; lw++) acc[lw] = rem[sw + lw];
            int cnt = s_cnt;
            int kin = 0;
            bool dn = false;
            int istop = 0;
            for (int lw = 0; lw < 8 && !dn; lw++) {
                int base = seg + lw * 32;
                int nb = P - base;
                if (nb <= 0) break;
                unsigned vm = (nb >= 32) ? 0xFFFFFFFFu : ((1u << nb) - 1u);
                unsigned alive = ~acc[lw] & vm;
                while (alive) {
                    int b = __ffs(alive) - 1;
                    int i = base + b;
                    cnt++;
                    keptlist[kin++] = i;     // all lanes: same addr, same value
                    if (cnt >= MAXOUT) { istop = i; dn = true; break; }
                    int r = i - seg;
                    #pragma unroll
                    for (int w2 = 0; w2 < 8; w2++) acc[w2] |= segmat[r * 8 + w2];
                    alive = (~acc[lw]) & vm & (0xFFFFFFFEu << b);
                }
            }
            if (lane == 0) {
                #pragma unroll
                for (int lw = 0; lw < 8; lw++) rem[sw + lw] = acc[lw];
                s_cnt = cnt;
                s_kin = kin;
                if (dn) { s_done = 1; s_istop = istop; }
            }
        }
        __syncthreads();

        if (s_done) break;
        int kin = s_kin;

        // (c) cross suppression: later j vs this segment's kept list
        for (int j = seg + SEG + t; j < P; j += 1024) {
            if ((rem[j >> 5] >> (j & 31)) & 1) continue;
            float4 bj = bbox[j];
            float aj = (bj.z - bj.x) * (bj.w - bj.y);
            for (int k = 0; k < kin; k++) {
                float4 bi = bbox[keptlist[k]];     // warp-uniform -> broadcast
                float ih = fmaxf(fminf(bi.z, bj.z) - fmaxf(bi.x, bj.x), 0.0f);
                float iw = fmaxf(fminf(bi.w, bj.w) - fmaxf(bi.y, bj.y), 0.0f);
                float inter = ih * iw;
                float ai = (bi.z - bi.x) * (bi.w - bi.y);
                float iou = inter / (ai + aj - inter + 1e-9f);
                if (iou > NMS_THR) {
                    atomicOr(&rem[j >> 5], 1u << (j & 31));
                    break;
                }
            }
        }
        __syncthreads();
    }
    __syncthreads();
    const int i_stop = s_istop;   // NANCH if cap never reached

    // ---- phase 4: ballot-scan ranking + candidate emission -------------------
    bool f0 = (t <= i_stop) && !((rem[t >> 5] >> (t & 31)) & 1) && (sc0 > SCORE_THR);
    int p1 = t + 1024;
    bool f1 = (p1 <= i_stop) && !((rem[p1 >> 5] >> (p1 & 31)) & 1) && (sc1 > SCORE_THR);
    unsigned b0 = __ballot_sync(FULLMASK, f0);
    unsigned b1 = __ballot_sync(FULLMASK, f1);
    if (lane == 0) { ballots[warp] = b0; ballots[32 + warp] = b1; }
    __syncthreads();
    if (t < 64) {
        int s = 0;
        for (int u = 0; u < t; u++) s += __popc(ballots[u]);
        wpre[t] = s;
    }
    __syncthreads();

    unsigned lmask = (1u << lane) - 1u;
    if (f0) {
        int rank = wpre[warp] + __popc(b0 & lmask);
        int flatc = c * MAXOUT + rank;
        g_cand[flatc] = ((k0 >> 32) << 32) | (unsigned)(0xFFFFFFFFu - (unsigned)flatc);
        ((float4*)g_cand_box)[flatc] = bbox[t];
    }
    if (f1) {
        int rank = wpre[32 + warp] + __popc(b1 & lmask);
        int flatc = c * MAXOUT + rank;
        g_cand[flatc] = ((k1 >> 32) << 32) | (unsigned)(0xFFFFFFFFu - (unsigned)flatc);
        ((float4*)g_cand_box)[flatc] = bbox[p1];
    }
    if (t == 0) {
        int total = 0;
        #pragma unroll
        for (int u = 0; u < 64; u++) total += __popc(ballots[u]);
        g_cnt[c] = total;
        g_best[c] = ((k0 >> 32) << 32) | (unsigned)(0xFFFFFFFFu - (unsigned)c);
        ((float4*)g_best_box)[c] = bbox[0];
    }
}

// ---------------------------------------------------------------------------
// Kernel 2: global top-200 via histogram select + exact ranking (dense keys)
// ---------------------------------------------------------------------------
__global__ __launch_bounds__(1024, 1)
void topk_kernel(float* __restrict__ out)
{
    __shared__ ull subkeys[4224];
    __shared__ ull slots[MAXOUT];
    __shared__ int hist[256];
    __shared__ int scnt_s[NCLS];
    __shared__ int s_m, s_bstar;

    const int t = threadIdx.x;

    if (t < 256) hist[t] = 0;
    if (t < MAXOUT) slots[t] = 0ULL;
    if (t < NCLS) scnt_s[t] = g_cnt[t];
    if (t == 0) { s_m = 0; s_bstar = 0; }
    __syncthreads();

    ull myk[5];
    #pragma unroll
    for (int rep = 0; rep < 5; rep++) {
        int i = t + rep * 1024;
        ull key = 0ULL;
        if (i < CAND_CAP) {
            int c = i / MAXOUT;
            int r = i - c * MAXOUT;
            if (r < scnt_s[c]) key = g_cand[i];
        }
        myk[rep] = key;
        if (key) {
            unsigned sb = (unsigned)(key >> 32);
            int bin = (int)((sb - 0x3F000000u) >> 15);
            bin = min(max(bin, 0), 255);
            atomicAdd(&hist[bin], 1);
        }
    }
    __syncthreads();

    // parallel suffix selection of boundary bin
    if (t < 256) {
        int sum = 0;
        for (int b = t; b < 256; b++) sum += hist[b];
        if (sum >= MAXOUT) atomicMax(&s_bstar, t);
    }
    __syncthreads();
    int bstar = s_bstar;

    // dense compaction of boundary superset
    #pragma unroll
    for (int rep = 0; rep < 5; rep++) {
        ull key = myk[rep];
        if (key) {
            unsigned sb = (unsigned)(key >> 32);
            int bin = (int)((sb - 0x3F000000u) >> 15);
            bin = min(max(bin, 0), 255);
            if (bin >= bstar) {
                int pos = atomicAdd(&s_m, 1);
                subkeys[pos] = key;
            }
        }
    }
    __syncthreads();
    int M = s_m;

    // exact rank within superset (keys unique)
    for (int s = t; s < M; s += 1024) {
        ull k = subkeys[s];
        int r = 0;
        for (int m = 0; m < M; m++)
            r += (subkeys[m] > k) ? 1 : 0;
        if (r < MAXOUT) slots[r] = k;
    }
    __syncthreads();

    if (t < MAXOUT) {
        float b0 = 0.f, b1 = 0.f, b2 = 0.f, b3 = 0.f, lab = 0.f, sc = 0.f;
        ull key = slots[t];
        if (key != 0ULL) {
            sc = __uint_as_float((unsigned)(key >> 32));
            unsigned flatc = 0xFFFFFFFFu - (unsigned)(key & 0xFFFFFFFFu);
            lab = (float)(flatc / MAXOUT);
            float4 bb = ((const float4*)g_cand_box)[flatc];
            b0 = fminf(fmaxf(bb.x, 0.f), 1.f);
            b1 = fminf(fmaxf(bb.y, 0.f), 1.f);
            b2 = fminf(fmaxf(bb.z, 0.f), 1.f);
            b3 = fminf(fmaxf(bb.w, 0.f), 1.f);
        } else if (t == 0 && M == 0) {
            ull best = 0ULL;
            #pragma unroll
            for (int c2 = 0; c2 < NCLS; c2++) {
                ull v = g_best[c2];
                if (v > best) best = v;
            }
            float s = __uint_as_float((unsigned)(best >> 32));
            if (s >= 0.001f) {
                sc = s;
                int c2 = (int)(0xFFFFFFFFu - (unsigned)(best & 0xFFFFFFFFu));
                lab = (float)c2;
                float4 bb = ((const float4*)g_best_box)[c2];
                b0 = fminf(fmaxf(bb.x, 0.f), 1.f);
                b1 = fminf(fmaxf(bb.y, 0.f), 1.f);
                b2 = fminf(fmaxf(bb.z, 0.f), 1.f);
                b3 = fminf(fmaxf(bb.w, 0.f), 1.f);
            }
        }
        out[t * 4 + 0] = b0;
        out[t * 4 + 1] = b1;
        out[t * 4 + 2] = b2;
        out[t * 4 + 3] = b3;
        out[MAXOUT * 4 + t] = lab;
        out[MAXOUT * 5 + t] = sc;
    }
}

extern "C" void kernel_launch(void* const* d_in, const int* in_sizes, int n_in,
                              void* d_out, int out_size)
{
    (void)in_sizes; (void)n_in; (void)out_size;
    const float* rois   = (const float*)d_in[0];
    const float* deltas = (const float*)d_in[1];
    const float* probs  = (const float*)d_in[2];
    float* out = (float*)d_out;

    score_kernel<<<NANCH / 256, 256>>>(probs);
    class_nms_kernel<<<NCLS, 1024>>>(rois, deltas);
    topk_kernel<<<1, 1024>>>(out);
}

// round 9
// speedup vs baseline: 1.4923x; 1.0752x over previous
#include <cuda_runtime.h>

#define NANCH 2048
#define NCLS 21
#define MAXOUT 200
#define NMS_THR 0.5f
#define SCORE_THR 0.5f
#define CAND_CAP (NCLS * MAXOUT)   /* 4200 */
#define FULLMASK 0xFFFFFFFFu
#define SEG 256

typedef unsigned long long ull;

// Scratch (no allocations allowed)
__device__ float g_scoreT[NCLS * NANCH];    // transposed masked scores
__device__ ull   g_cand[CAND_CAP];          // per-class rank-ordered candidate keys
__device__ float g_cand_box[CAND_CAP * 4];  // matching boxes
__device__ int   g_cnt[NCLS];
__device__ ull   g_best[NCLS];              // per-class fallback
__device__ float g_best_box[NCLS * 4];

// ---------------------------------------------------------------------------
// Kernel 0: per-anchor argmax mask + transposed score write (done ONCE).
// ---------------------------------------------------------------------------
__global__ __launch_bounds__(128)
void score_kernel(const float* __restrict__ probs)
{
    __shared__ float sp[128 * NCLS];
    const int t = threadIdx.x;
    const int base = blockIdx.x * 128;

    const float* src = probs + base * NCLS;
    #pragma unroll
    for (int i = t; i < 128 * NCLS; i += 128) sp[i] = src[i];
    __syncthreads();

    const float* pr = sp + t * NCLS;
    float p0 = pr[0];
    float m = pr[1];
    #pragma unroll
    for (int k = 2; k < NCLS; k++) m = fmaxf(m, pr[k]);
    bool valid = (m > p0);

    int n = base + t;
    #pragma unroll
    for (int c = 0; c < NCLS; c++)
        g_scoreT[c * NANCH + n] = valid ? pr[c] : 0.0f;
}

__device__ __forceinline__ ull cmpx(ull v, ull o, bool takeMax) {
    return takeMax ? (v > o ? v : o) : (v < o ? v : o);
}

// Register bitonic tail: j=32 (in-thread) then j=16..1 (shfl_xor).
__device__ __forceinline__ void reg_tail(ull& lo, ull& hi, int e_lo, int k, int lane) {
    if (k >= 64) {
        bool desc = ((e_lo & k) == 0);
        if ((lo < hi) == desc) { ull tmp = lo; lo = hi; hi = tmp; }
    }
    #pragma unroll
    for (int j = 16; j >= 1; j >>= 1) {
        if (j > (k >> 1)) continue;
        bool is_low = ((lane & j) == 0);
        {
            ull o = __shfl_xor_sync(FULLMASK, lo, j);
            bool desc = ((e_lo & k) == 0);
            lo = cmpx(lo, o, is_low == desc);
        }
        {
            ull o = __shfl_xor_sync(FULLMASK, hi, j);
            bool desc = (((e_lo + 32) & k) == 0);
            hi = cmpx(hi, o, is_low == desc);
        }
    }
}

__device__ __forceinline__ float4 dec_box(const float* __restrict__ rois,
                                          const float* __restrict__ deltas,
                                          int c, int n)
{
    float4 rb = ((const float4*)rois)[n];
    const float* dd = deltas + n * (NCLS * 4) + c * 4;
    float dy = dd[0] * 0.1f;
    float dx = dd[1] * 0.1f;
    float dh = dd[2] * 0.2f;
    float dw = dd[3] * 0.2f;
    float h  = rb.z - rb.x;
    float w  = rb.w - rb.y;
    float cy = rb.x + 0.5f * h;
    float cx = rb.y + 0.5f * w;
    float nh = __expf(dh) * h;
    float nw = __expf(dw) * w;
    float ncy = dy * h + cy;
    float ncx = dx * w + cx;
    return make_float4(ncy - 0.5f * nh, ncx - 0.5f * nw,
                       ncy + 0.5f * nh, ncx + 0.5f * nw);
}

// ---------------------------------------------------------------------------
// Kernel 1: one block per class, 1024 threads.
// Compact candidates -> bitonic sort of 1024 (2048 fallback) -> segment NMS.
// ---------------------------------------------------------------------------
__global__ __launch_bounds__(1024, 1)
void class_nms_kernel(const float* __restrict__ rois,
                      const float* __restrict__ deltas)
{
    __shared__ __align__(16) unsigned char sraw[32768];  // keys, then float4 boxes
    __shared__ unsigned segmat[SEG * 8];
    __shared__ int keptlist[SEG];
    __shared__ unsigned rem[64];
    __shared__ unsigned ballots[64];
    __shared__ int wpre[64];
    __shared__ ull maxw[32];
    __shared__ ull s_gmax;
    __shared__ int s_P, s_cnt, s_kin, s_done, s_istop;

    float4* bbox = (float4*)sraw;
    ull*    skey = (ull*)sraw;             // overlaps bbox (freed before decode)

    const int c = blockIdx.x;
    const int t = threadIdx.x;
    const int lane = t & 31;
    const int warp = t >> 5;
    const int e_lo = warp * 64 + lane;
    const int e_hi = e_lo + 32;

    // ---- phase 0: scores -> keys, candidate flags, global max ----------------
    const float* scT = g_scoreT + c * NANCH;
    float sA = scT[t];
    float sB = scT[t + 1024];
    ull keyA = ((ull)__float_as_uint(sA) << 32) | (unsigned)(NANCH - 1 - t);
    ull keyB = ((ull)__float_as_uint(sB) << 32) | (unsigned)(NANCH - 1 - (t + 1024));
    bool fA = sA > SCORE_THR;
    bool fB = sB > SCORE_THR;

    {   // block max key (fallback when P == 0)
        ull km = keyA > keyB ? keyA : keyB;
        #pragma unroll
        for (int d = 16; d >= 1; d >>= 1) {
            ull o = __shfl_xor_sync(FULLMASK, km, d);
            if (o > km) km = o;
        }
        if (lane == 0) maxw[warp] = km;
    }

    // ---- compaction rank via ballots -----------------------------------------
    unsigned bA = __ballot_sync(FULLMASK, fA);
    unsigned bB = __ballot_sync(FULLMASK, fB);
    if (lane == 0) { ballots[warp] = bA; ballots[32 + warp] = bB; }
    if (t == 0) { s_cnt = 0; s_done = 0; s_istop = NANCH; }
    __syncthreads();
    if (t < 64) {
        int s = 0;
        for (int u = 0; u < t; u++) s += __popc(ballots[u]);
        wpre[t] = s;
    }
    if (t == 0) {
        int tot = 0;
        #pragma unroll
        for (int u = 0; u < 64; u++) tot += __popc(ballots[u]);
        s_P = tot;
        ull gm = maxw[0];
        #pragma unroll
        for (int u = 1; u < 32; u++) if (maxw[u] > gm) gm = maxw[u];
        s_gmax = gm;
    }
    __syncthreads();
    const int P = s_P;
    const int nsort = (P <= 1024) ? 1024 : 2048;

    // scatter candidates (order irrelevant: full sort follows)
    unsigned lmaskc = (1u << lane) - 1u;
    if (fA) skey[wpre[warp] + __popc(bA & lmaskc)] = keyA;
    if (fB) skey[wpre[32 + warp] + __popc(bB & lmaskc)] = keyB;
    for (int p = P + t; p < nsort; p += 1024) skey[p] = 0ULL;   // pad
    if (t < 64) rem[t] = 0;
    __syncthreads();

    // ---- phase 1: hybrid bitonic sort on nsort keys (descending) -------------
    if (e_lo < nsort) {
        ull lo = skey[e_lo];
        ull hi = skey[e_hi];
        #pragma unroll
        for (int k = 2; k <= 64; k <<= 1)
            reg_tail(lo, hi, e_lo, k, lane);
        skey[e_lo] = lo; skey[e_hi] = hi;
    }
    __syncthreads();

    for (int k = 128; k <= nsort; k <<= 1) {
        for (int j = k >> 1; j >= 64; j >>= 1) {
            if (t < (nsort >> 1)) {
                int idx = ((t & ~(j - 1)) << 1) | (t & (j - 1));
                int pid = idx | j;
                ull a = skey[idx];
                ull b = skey[pid];
                bool desc = ((idx & k) == 0);
                if ((a < b) == desc) { skey[idx] = b; skey[pid] = a; }
            }
            __syncthreads();
        }
        if (e_lo < nsort) {
            ull lo = skey[e_lo], hi = skey[e_hi];
            reg_tail(lo, hi, e_lo, k, lane);
            skey[e_lo] = lo; skey[e_hi] = hi;
        }
        __syncthreads();
    }

    ull k0 = skey[t];
    ull k1 = (nsort == 2048) ? skey[t + 1024] : 0ULL;
    __syncthreads();                       // keys in regs; region freed -> bbox

    // ---- phase 2: decode boxes (sorted candidate order) ----------------------
    #pragma unroll
    for (int rep = 0; rep < 2; rep++) {
        int p = t + rep * 1024;
        if (p < P) {
            ull key = rep ? k1 : k0;
            int n = NANCH - 1 - (int)(key & 0xFFFFFFFFu);
            bbox[p] = dec_box(rois, deltas, c, n);
        }
    }
    __syncthreads();

    // per-class fallback best (global max box)
    if (t == 0) {
        ull gm = s_gmax;
        g_best[c] = ((gm >> 32) << 32) | (unsigned)(0xFFFFFFFFu - (unsigned)c);
        if (P > 0) {
            ((float4*)g_best_box)[c] = bbox[0];   // P>0 => global max is rank 0
        } else {
            int n = NANCH - 1 - (int)(gm & 0xFFFFFFFFu);
            ((float4*)g_best_box)[c] = dec_box(rois, deltas, c, n);
        }
    }

    // ---- phase 3: segmented NMS ----------------------------------------------
    for (int seg = 0; seg < P; seg += SEG) {
        // (a) intra-segment matrix build (uniform dead-column skip)
        {
            int w = t >> 7;
            int r0 = (t & 127) * 2;
            int r1 = r0 + 1;
            int i0 = seg + r0;
            int i1 = seg + r1;
            int jbase = seg + w * 32;
            int nb = P - jbase;
            unsigned vm = (nb >= 32) ? 0xFFFFFFFFu : ((nb <= 0) ? 0u : ((1u << nb) - 1u));
            unsigned valid = vm & ~rem[(unsigned)jbase >> 5];   // warp-uniform
            int rw0 = r0 >> 5, rw1 = r1 >> 5;
            unsigned m0 = (w > rw0) ? vm : ((w < rw0) ? 0u : ((0xFFFFFFFEu << (r0 & 31)) & vm));
            unsigned m1 = (w > rw1) ? vm : ((w < rw1) ? 0u : ((0xFFFFFFFEu << (r1 & 31)) & vm));
            if (i0 >= P || ((rem[i0 >> 5] >> (i0 & 31)) & 1)) m0 = 0;
            if (i1 >= P || ((rem[i1 >> 5] >> (i1 & 31)) & 1)) m1 = 0;
            if ((m0 | m1) && valid) {
                float4 b0 = bbox[i0 < P ? i0 : 0];
                float4 b1 = bbox[i1 < P ? i1 : 0];
                float a0 = (b0.z - b0.x) * (b0.w - b0.y);
                float a1 = (b1.z - b1.x) * (b1.w - b1.y);
                unsigned bits0 = 0, bits1 = 0;
                #pragma unroll
                for (int jl = 0; jl < 32; jl++) {
                    if (!((valid >> jl) & 1)) continue;   // uniform branch
                    float4 bj = bbox[jbase + jl];
                    float aj = (bj.z - bj.x) * (bj.w - bj.y);
                    {
                        float ih = fmaxf(fminf(b0.z, bj.z) - fmaxf(b0.x, bj.x), 0.0f);
                        float iw = fmaxf(fminf(b0.w, bj.w) - fmaxf(b0.y, bj.y), 0.0f);
                        float inter = ih * iw;
                        float iou = inter / (a0 + aj - inter + 1e-9f);
                        bits0 |= (iou > NMS_THR ? 1u : 0u) << jl;
                    }
                    {
                        float ih = fmaxf(fminf(b1.z, bj.z) - fmaxf(b1.x, bj.x), 0.0f);
                        float iw = fmaxf(fminf(b1.w, bj.w) - fmaxf(b1.y, bj.y), 0.0f);
                        float inter = ih * iw;
                        float iou = inter / (a1 + aj - inter + 1e-9f);
                        bits1 |= (iou > NMS_THR ? 1u : 0u) << jl;
                    }
                }
                segmat[r0 * 8 + w] = bits0 & m0;
                segmat[r1 * 8 + w] = bits1 & m1;
            } else {
                segmat[r0 * 8 + w] = 0;
                segmat[r1 * 8 + w] = 0;
            }
        }
        __syncthreads();

        // (b) warp-serial greedy scan of this segment (warp 0, uniform lanes)
        if (warp == 0) {
            unsigned acc[8];
            int sw = seg >> 5;
            #pragma unroll
            for (int lw = 0; lw < 8; lw++) acc[lw] = rem[sw + lw];
            int cnt = s_cnt;
            int kin = 0;
            bool dn = false;
            int istop = 0;
            for (int lw = 0; lw < 8 && !dn; lw++) {
                int base = seg + lw * 32;
                int nb = P - base;
                if (nb <= 0) break;
                unsigned vm = (nb >= 32) ? 0xFFFFFFFFu : ((1u << nb) - 1u);
                unsigned alive = ~acc[lw] & vm;
                while (alive) {
                    int b = __ffs(alive) - 1;
                    int i = base + b;
                    cnt++;
                    keptlist[kin++] = i;
                    if (cnt >= MAXOUT) { istop = i; dn = true; break; }
                    int r = i - seg;
                    #pragma unroll
                    for (int w2 = 0; w2 < 8; w2++) acc[w2] |= segmat[r * 8 + w2];
                    alive = (~acc[lw]) & vm & (0xFFFFFFFEu << b);
                }
            }
            if (lane == 0) {
                #pragma unroll
                for (int lw = 0; lw < 8; lw++) rem[sw + lw] = acc[lw];
                s_cnt = cnt;
                s_kin = kin;
                if (dn) { s_done = 1; s_istop = istop; }
            }
        }
        __syncthreads();

        if (s_done) break;
        int kin = s_kin;

        // (c) cross suppression: later j vs this segment's kept list
        for (int j = seg + SEG + t; j < P; j += 1024) {
            if ((rem[j >> 5] >> (j & 31)) & 1) continue;
            float4 bj = bbox[j];
            float aj = (bj.z - bj.x) * (bj.w - bj.y);
            for (int k = 0; k < kin; k++) {
                float4 bi = bbox[keptlist[k]];
                float ih = fmaxf(fminf(bi.z, bj.z) - fmaxf(bi.x, bj.x), 0.0f);
                float iw = fmaxf(fminf(bi.w, bj.w) - fmaxf(bi.y, bj.y), 0.0f);
                float inter = ih * iw;
                float ai = (bi.z - bi.x) * (bi.w - bi.y);
                float iou = inter / (ai + aj - inter + 1e-9f);
                if (iou > NMS_THR) {
                    atomicOr(&rem[j >> 5], 1u << (j & 31));
                    break;
                }
            }
        }
        __syncthreads();
    }
    __syncthreads();
    const int i_stop = s_istop;

    // ---- phase 4: ballot-scan ranking + candidate emission --------------------
    int p1 = t + 1024;
    bool f0 = (t < P)  && (t <= i_stop)  && !((rem[t >> 5] >> (t & 31)) & 1);
    bool f1 = (p1 < P) && (p1 <= i_stop) && !((rem[p1 >> 5] >> (p1 & 31)) & 1);
    unsigned b0 = __ballot_sync(FULLMASK, f0);
    unsigned b1 = __ballot_sync(FULLMASK, f1);
    if (lane == 0) { ballots[warp] = b0; ballots[32 + warp] = b1; }
    __syncthreads();
    if (t < 64) {
        int s = 0;
        for (int u = 0; u < t; u++) s += __popc(ballots[u]);
        wpre[t] = s;
    }
    __syncthreads();

    unsigned lmask = (1u << lane) - 1u;
    if (f0) {
        int rank = wpre[warp] + __popc(b0 & lmask);
        int flatc = c * MAXOUT + rank;
        g_cand[flatc] = ((k0 >> 32) << 32) | (unsigned)(0xFFFFFFFFu - (unsigned)flatc);
        ((float4*)g_cand_box)[flatc] = bbox[t];
    }
    if (f1) {
        int rank = wpre[32 + warp] + __popc(b1 & lmask);
        int flatc = c * MAXOUT + rank;
        g_cand[flatc] = ((k1 >> 32) << 32) | (unsigned)(0xFFFFFFFFu - (unsigned)flatc);
        ((float4*)g_cand_box)[flatc] = bbox[p1];
    }
    if (t == 0) {
        int total = 0;
        #pragma unroll
        for (int u = 0; u < 64; u++) total += __popc(ballots[u]);
        g_cnt[c] = total;
    }
}

// ---------------------------------------------------------------------------
// Kernel 2: global top-200 via histogram select + exact ranking (dense keys)
// ---------------------------------------------------------------------------
__global__ __launch_bounds__(1024, 1)
void topk_kernel(float* __restrict__ out)
{
    __shared__ ull subkeys[4224];
    __shared__ ull slots[MAXOUT];
    __shared__ int hist[256];
    __shared__ int scnt_s[NCLS];
    __shared__ int s_m, s_bstar;

    const int t = threadIdx.x;

    if (t < 256) hist[t] = 0;
    if (t < MAXOUT) slots[t] = 0ULL;
    if (t < NCLS) scnt_s[t] = g_cnt[t];
    if (t == 0) { s_m = 0; s_bstar = 0; }
    __syncthreads();

    ull myk[5];
    #pragma unroll
    for (int rep = 0; rep < 5; rep++) {
        int i = t + rep * 1024;
        ull key = 0ULL;
        if (i < CAND_CAP) {
            int c = i / MAXOUT;
            int r = i - c * MAXOUT;
            if (r < scnt_s[c]) key = g_cand[i];
        }
        myk[rep] = key;
        if (key) {
            unsigned sb = (unsigned)(key >> 32);
            int bin = (int)((sb - 0x3F000000u) >> 15);
            bin = min(max(bin, 0), 255);
            atomicAdd(&hist[bin], 1);
        }
    }
    __syncthreads();

    if (t < 256) {
        int sum = 0;
        for (int b = t; b < 256; b++) sum += hist[b];
        if (sum >= MAXOUT) atomicMax(&s_bstar, t);
    }
    __syncthreads();
    int bstar = s_bstar;

    #pragma unroll
    for (int rep = 0; rep < 5; rep++) {
        ull key = myk[rep];
        if (key) {
            unsigned sb = (unsigned)(key >> 32);
            int bin = (int)((sb - 0x3F000000u) >> 15);
            bin = min(max(bin, 0), 255);
            if (bin >= bstar) {
                int pos = atomicAdd(&s_m, 1);
                subkeys[pos] = key;
            }
        }
    }
    __syncthreads();
    int M = s_m;

    for (int s = t; s < M; s += 1024) {
        ull k = subkeys[s];
        int r = 0;
        for (int m = 0; m < M; m++)
            r += (subkeys[m] > k) ? 1 : 0;
        if (r < MAXOUT) slots[r] = k;
    }
    __syncthreads();

    if (t < MAXOUT) {
        float b0 = 0.f, b1 = 0.f, b2 = 0.f, b3 = 0.f, lab = 0.f, sc = 0.f;
        ull key = slots[t];
        if (key != 0ULL) {
            sc = __uint_as_float((unsigned)(key >> 32));
            unsigned flatc = 0xFFFFFFFFu - (unsigned)(key & 0xFFFFFFFFu);
            lab = (float)(flatc / MAXOUT);
            float4 bb = ((const float4*)g_cand_box)[flatc];
            b0 = fminf(fmaxf(bb.x, 0.f), 1.f);
            b1 = fminf(fmaxf(bb.y, 0.f), 1.f);
            b2 = fminf(fmaxf(bb.z, 0.f), 1.f);
            b3 = fminf(fmaxf(bb.w, 0.f), 1.f);
        } else if (t == 0 && M == 0) {
            ull best = 0ULL;
            #pragma unroll
            for (int c2 = 0; c2 < NCLS; c2++) {
                ull v = g_best[c2];
                if (v > best) best = v;
            }
            float s = __uint_as_float((unsigned)(best >> 32));
            if (s >= 0.001f) {
                sc = s;
                int c2 = (int)(0xFFFFFFFFu - (unsigned)(best & 0xFFFFFFFFu));
                lab = (float)c2;
                float4 bb = ((const float4*)g_best_box)[c2];
                b0 = fminf(fmaxf(bb.x, 0.f), 1.f);
                b1 = fminf(fmaxf(bb.y, 0.f), 1.f);
                b2 = fminf(fmaxf(bb.z, 0.f), 1.f);
                b3 = fminf(fmaxf(bb.w, 0.f), 1.f);
            }
        }
        out[t * 4 + 0] = b0;
        out[t * 4 + 1] = b1;
        out[t * 4 + 2] = b2;
        out[t * 4 + 3] = b3;
        out[MAXOUT * 4 + t] = lab;
        out[MAXOUT * 5 + t] = sc;
    }
}

extern "C" void kernel_launch(void* const* d_in, const int* in_sizes, int n_in,
                              void* d_out, int out_size)
{
    (void)in_sizes; (void)n_in; (void)out_size;
    const float* rois   = (const float*)d_in[0];
    const float* deltas = (const float*)d_in[1];
    const float* probs  = (const float*)d_in[2];
    float* out = (float*)d_out;

    score_kernel<<<NANCH / 128, 128>>>(probs);
    class_nms_kernel<<<NCLS, 1024>>>(rois, deltas);
    topk_kernel<<<1, 1024>>>(out);
}

// round 10
// speedup vs baseline: 1.9437x; 1.3025x over previous
#include <cuda_runtime.h>

#define NANCH 2048
#define NCLS 21
#define MAXOUT 200
#define NMS_THR 0.5f
#define SCORE_THR 0.5f
#define CAND_CAP (NCLS * MAXOUT)   /* 4200 */
#define FULLMASK 0xFFFFFFFFu
#define SEG 256

typedef unsigned long long ull;

// Scratch (no allocations allowed)
__device__ float g_scoreT[NCLS * NANCH];    // transposed masked scores
__device__ ull   g_cand[CAND_CAP];          // per-class rank-ordered candidate keys
__device__ float g_cand_box[CAND_CAP * 4];  // matching boxes
__device__ int   g_cnt[NCLS];
__device__ ull   g_best[NCLS];              // per-class fallback
__device__ float g_best_box[NCLS * 4];

// IoU > 0.5 test without division:
// inter/(den) > 0.5  <=>  2*inter > den   (den > 0, 2*inter exact)

// ---------------------------------------------------------------------------
// Kernel 0: per-anchor argmax mask + transposed score write (done ONCE).
// ---------------------------------------------------------------------------
__global__ __launch_bounds__(128)
void score_kernel(const float* __restrict__ probs)
{
    __shared__ float sp[128 * NCLS];
    const int t = threadIdx.x;
    const int base = blockIdx.x * 128;

    const float* src = probs + base * NCLS;
    #pragma unroll
    for (int i = t; i < 128 * NCLS; i += 128) sp[i] = src[i];
    __syncthreads();

    const float* pr = sp + t * NCLS;
    float p0 = pr[0];
    float m = pr[1];
    #pragma unroll
    for (int k = 2; k < NCLS; k++) m = fmaxf(m, pr[k]);
    bool valid = (m > p0);

    int n = base + t;
    #pragma unroll
    for (int c = 0; c < NCLS; c++)
        g_scoreT[c * NANCH + n] = valid ? pr[c] : 0.0f;
}

__device__ __forceinline__ ull cmpx(ull v, ull o, bool takeMax) {
    return takeMax ? (v > o ? v : o) : (v < o ? v : o);
}

// Register bitonic tail: j=32 (in-thread) then j=16..1 (shfl_xor).
__device__ __forceinline__ void reg_tail(ull& lo, ull& hi, int e_lo, int k, int lane) {
    if (k >= 64) {
        bool desc = ((e_lo & k) == 0);
        if ((lo < hi) == desc) { ull tmp = lo; lo = hi; hi = tmp; }
    }
    #pragma unroll
    for (int j = 16; j >= 1; j >>= 1) {
        if (j > (k >> 1)) continue;
        bool is_low = ((lane & j) == 0);
        {
            ull o = __shfl_xor_sync(FULLMASK, lo, j);
            bool desc = ((e_lo & k) == 0);
            lo = cmpx(lo, o, is_low == desc);
        }
        {
            ull o = __shfl_xor_sync(FULLMASK, hi, j);
            bool desc = (((e_lo + 32) & k) == 0);
            hi = cmpx(hi, o, is_low == desc);
        }
    }
}

__device__ __forceinline__ float4 dec_box(const float* __restrict__ rois,
                                          const float* __restrict__ deltas,
                                          int c, int n)
{
    float4 rb = ((const float4*)rois)[n];
    const float* dd = deltas + n * (NCLS * 4) + c * 4;
    float dy = dd[0] * 0.1f;
    float dx = dd[1] * 0.1f;
    float dh = dd[2] * 0.2f;
    float dw = dd[3] * 0.2f;
    float h  = rb.z - rb.x;
    float w  = rb.w - rb.y;
    float cy = rb.x + 0.5f * h;
    float cx = rb.y + 0.5f * w;
    float nh = __expf(dh) * h;
    float nw = __expf(dw) * w;
    float ncy = dy * h + cy;
    float ncx = dx * w + cx;
    return make_float4(ncy - 0.5f * nh, ncx - 0.5f * nw,
                       ncy + 0.5f * nh, ncx + 0.5f * nw);
}

// ---------------------------------------------------------------------------
// Kernel 1: one block per class, 1024 threads.
// Compact candidates -> bitonic sort of 1024 (2048 fallback) -> segment NMS.
// ---------------------------------------------------------------------------
__global__ __launch_bounds__(1024, 1)
void class_nms_kernel(const float* __restrict__ rois,
                      const float* __restrict__ deltas)
{
    __shared__ __align__(16) unsigned char sraw[32768];  // keys, then float4 boxes
    __shared__ unsigned segmat[SEG * 8];
    __shared__ int keptlist[SEG];
    __shared__ unsigned rem[64];
    __shared__ unsigned ballots[64];
    __shared__ int wpre[64];
    __shared__ ull maxw[32];
    __shared__ ull s_gmax;
    __shared__ int s_P, s_cnt, s_kin, s_done, s_istop;

    float4* bbox = (float4*)sraw;
    ull*    skey = (ull*)sraw;             // overlaps bbox (freed before decode)

    const int c = blockIdx.x;
    const int t = threadIdx.x;
    const int lane = t & 31;
    const int warp = t >> 5;
    const int e_lo = warp * 64 + lane;
    const int e_hi = e_lo + 32;

    // ---- phase 0: scores -> keys, candidate flags, global max ----------------
    const float* scT = g_scoreT + c * NANCH;
    float sA = scT[t];
    float sB = scT[t + 1024];
    ull keyA = ((ull)__float_as_uint(sA) << 32) | (unsigned)(NANCH - 1 - t);
    ull keyB = ((ull)__float_as_uint(sB) << 32) | (unsigned)(NANCH - 1 - (t + 1024));
    bool fA = sA > SCORE_THR;
    bool fB = sB > SCORE_THR;

    {   // block max key (fallback when P == 0)
        ull km = keyA > keyB ? keyA : keyB;
        #pragma unroll
        for (int d = 16; d >= 1; d >>= 1) {
            ull o = __shfl_xor_sync(FULLMASK, km, d);
            if (o > km) km = o;
        }
        if (lane == 0) maxw[warp] = km;
    }

    // ---- compaction rank via ballots -----------------------------------------
    unsigned bA = __ballot_sync(FULLMASK, fA);
    unsigned bB = __ballot_sync(FULLMASK, fB);
    if (lane == 0) { ballots[warp] = bA; ballots[32 + warp] = bB; }
    if (t == 0) { s_cnt = 0; s_done = 0; s_istop = NANCH; }
    __syncthreads();
    if (t < 64) {
        int s = 0;
        for (int u = 0; u < t; u++) s += __popc(ballots[u]);
        wpre[t] = s;
    }
    if (t == 0) {
        int tot = 0;
        #pragma unroll
        for (int u = 0; u < 64; u++) tot += __popc(ballots[u]);
        s_P = tot;
        ull gm = maxw[0];
        #pragma unroll
        for (int u = 1; u < 32; u++) if (maxw[u] > gm) gm = maxw[u];
        s_gmax = gm;
    }
    __syncthreads();
    const int P = s_P;
    const int nsort = (P <= 1024) ? 1024 : 2048;

    // scatter candidates (order irrelevant: full sort follows)
    unsigned lmaskc = (1u << lane) - 1u;
    if (fA) skey[wpre[warp] + __popc(bA & lmaskc)] = keyA;
    if (fB) skey[wpre[32 + warp] + __popc(bB & lmaskc)] = keyB;
    for (int p = P + t; p < nsort; p += 1024) skey[p] = 0ULL;   // pad
    if (t < 64) rem[t] = 0;
    __syncthreads();

    // ---- phase 1: hybrid bitonic sort on nsort keys (descending) -------------
    if (e_lo < nsort) {
        ull lo = skey[e_lo];
        ull hi = skey[e_hi];
        #pragma unroll
        for (int k = 2; k <= 64; k <<= 1)
            reg_tail(lo, hi, e_lo, k, lane);
        skey[e_lo] = lo; skey[e_hi] = hi;
    }
    __syncthreads();

    for (int k = 128; k <= nsort; k <<= 1) {
        for (int j = k >> 1; j >= 64; j >>= 1) {
            if (t < (nsort >> 1)) {
                int idx = ((t & ~(j - 1)) << 1) | (t & (j - 1));
                int pid = idx | j;
                ull a = skey[idx];
                ull b = skey[pid];
                bool desc = ((idx & k) == 0);
                if ((a < b) == desc) { skey[idx] = b; skey[pid] = a; }
            }
            __syncthreads();
        }
        if (e_lo < nsort) {
            ull lo = skey[e_lo], hi = skey[e_hi];
            reg_tail(lo, hi, e_lo, k, lane);
            skey[e_lo] = lo; skey[e_hi] = hi;
        }
        __syncthreads();
    }

    ull k0 = skey[t];
    ull k1 = (nsort == 2048) ? skey[t + 1024] : 0ULL;
    __syncthreads();                       // keys in regs; region freed -> bbox

    // ---- phase 2: decode boxes (sorted candidate order) ----------------------
    #pragma unroll
    for (int rep = 0; rep < 2; rep++) {
        int p = t + rep * 1024;
        if (p < P) {
            ull key = rep ? k1 : k0;
            int n = NANCH - 1 - (int)(key & 0xFFFFFFFFu);
            bbox[p] = dec_box(rois, deltas, c, n);
        }
    }
    __syncthreads();

    // per-class fallback best (global max box)
    if (t == 0) {
        ull gm = s_gmax;
        g_best[c] = ((gm >> 32) << 32) | (unsigned)(0xFFFFFFFFu - (unsigned)c);
        if (P > 0) {
            ((float4*)g_best_box)[c] = bbox[0];   // P>0 => global max is rank 0
        } else {
            int n = NANCH - 1 - (int)(gm & 0xFFFFFFFFu);
            ((float4*)g_best_box)[c] = dec_box(rois, deltas, c, n);
        }
    }

    // ---- phase 3: segmented NMS ----------------------------------------------
    for (int seg = 0; seg < P; seg += SEG) {
        // (a) intra-segment matrix build (uniform dead-column skip, div-free IoU)
        {
            int w = t >> 7;
            int r0 = (t & 127) * 2;
            int r1 = r0 + 1;
            int i0 = seg + r0;
            int i1 = seg + r1;
            int jbase = seg + w * 32;
            int nb = P - jbase;
            unsigned vm = (nb >= 32) ? 0xFFFFFFFFu : ((nb <= 0) ? 0u : ((1u << nb) - 1u));
            unsigned valid = vm & ~rem[(unsigned)jbase >> 5];   // warp-uniform
            int rw0 = r0 >> 5, rw1 = r1 >> 5;
            unsigned m0 = (w > rw0) ? vm : ((w < rw0) ? 0u : ((0xFFFFFFFEu << (r0 & 31)) & vm));
            unsigned m1 = (w > rw1) ? vm : ((w < rw1) ? 0u : ((0xFFFFFFFEu << (r1 & 31)) & vm));
            if (i0 >= P || ((rem[i0 >> 5] >> (i0 & 31)) & 1)) m0 = 0;
            if (i1 >= P || ((rem[i1 >> 5] >> (i1 & 31)) & 1)) m1 = 0;
            if ((m0 | m1) && valid) {
                float4 b0 = bbox[i0 < P ? i0 : 0];
                float4 b1 = bbox[i1 < P ? i1 : 0];
                float a0 = (b0.z - b0.x) * (b0.w - b0.y);
                float a1 = (b1.z - b1.x) * (b1.w - b1.y);
                unsigned bits0 = 0, bits1 = 0;
                #pragma unroll
                for (int jl = 0; jl < 32; jl++) {
                    if (!((valid >> jl) & 1)) continue;   // uniform branch
                    float4 bj = bbox[jbase + jl];
                    float aj = (bj.z - bj.x) * (bj.w - bj.y);
                    {
                        float ih = fmaxf(fminf(b0.z, bj.z) - fmaxf(b0.x, bj.x), 0.0f);
                        float iw = fmaxf(fminf(b0.w, bj.w) - fmaxf(b0.y, bj.y), 0.0f);
                        float inter = ih * iw;
                        float den = a0 + aj - inter + 1e-9f;
                        bits0 |= ((inter + inter > den) ? 1u : 0u) << jl;
                    }
                    {
                        float ih = fmaxf(fminf(b1.z, bj.z) - fmaxf(b1.x, bj.x), 0.0f);
                        float iw = fmaxf(fminf(b1.w, bj.w) - fmaxf(b1.y, bj.y), 0.0f);
                        float inter = ih * iw;
                        float den = a1 + aj - inter + 1e-9f;
                        bits1 |= ((inter + inter > den) ? 1u : 0u) << jl;
                    }
                }
                segmat[r0 * 8 + w] = bits0 & m0;
                segmat[r1 * 8 + w] = bits1 & m1;
            } else {
                segmat[r0 * 8 + w] = 0;
                segmat[r1 * 8 + w] = 0;
            }
        }
        __syncthreads();

        // (b) warp-serial greedy scan of this segment (warp 0, uniform lanes)
        if (warp == 0) {
            unsigned acc[8];
            int sw = seg >> 5;
            #pragma unroll
            for (int lw = 0; lw < 8; lw++) acc[lw] = rem[sw + lw];
            int cnt = s_cnt;
            int kin = 0;
            bool dn = false;
            int istop = 0;
            for (int lw = 0; lw < 8 && !dn; lw++) {
                int base = seg + lw * 32;
                int nb = P - base;
                if (nb <= 0) break;
                unsigned vm = (nb >= 32) ? 0xFFFFFFFFu : ((1u << nb) - 1u);
                unsigned alive = ~acc[lw] & vm;
                while (alive) {
                    int b = __ffs(alive) - 1;
                    int i = base + b;
                    cnt++;
                    keptlist[kin++] = i;
                    if (cnt >= MAXOUT) { istop = i; dn = true; break; }
                    int r = i - seg;
                    #pragma unroll
                    for (int w2 = 0; w2 < 8; w2++)
                        if (w2 >= lw)                     // earlier words provably 0
                            acc[w2] |= segmat[r * 8 + w2];
                    alive = (~acc[lw]) & vm & (0xFFFFFFFEu << b);
                }
            }
            if (lane == 0) {
                #pragma unroll
                for (int lw = 0; lw < 8; lw++) rem[sw + lw] = acc[lw];
                s_cnt = cnt;
                s_kin = kin;
                if (dn) { s_done = 1; s_istop = istop; }
            }
        }
        __syncthreads();

        if (s_done) break;
        int kin = s_kin;

        // (c) cross suppression: later j vs this segment's kept list (div-free)
        for (int j = seg + SEG + t; j < P; j += 1024) {
            if ((rem[j >> 5] >> (j & 31)) & 1) continue;
            float4 bj = bbox[j];
            float aj = (bj.z - bj.x) * (bj.w - bj.y);
            for (int k = 0; k < kin; k++) {
                float4 bi = bbox[keptlist[k]];
                float ih = fmaxf(fminf(bi.z, bj.z) - fmaxf(bi.x, bj.x), 0.0f);
                float iw = fmaxf(fminf(bi.w, bj.w) - fmaxf(bi.y, bj.y), 0.0f);
                float inter = ih * iw;
                float ai = (bi.z - bi.x) * (bi.w - bi.y);
                float den = ai + aj - inter + 1e-9f;
                if (inter + inter > den) {
                    atomicOr(&rem[j >> 5], 1u << (j & 31));
                    break;
                }
            }
        }
        __syncthreads();
    }
    __syncthreads();
    const int i_stop = s_istop;

    // ---- phase 4: ballot-scan ranking + candidate emission --------------------
    int p1 = t + 1024;
    bool f0 = (t < P)  && (t <= i_stop)  && !((rem[t >> 5] >> (t & 31)) & 1);
    bool f1 = (p1 < P) && (p1 <= i_stop) && !((rem[p1 >> 5] >> (p1 & 31)) & 1);
    unsigned b0 = __ballot_sync(FULLMASK, f0);
    unsigned b1 = __ballot_sync(FULLMASK, f1);
    if (lane == 0) { ballots[warp] = b0; ballots[32 + warp] = b1; }
    __syncthreads();
    if (t < 64) {
        int s = 0;
        for (int u = 0; u < t; u++) s += __popc(ballots[u]);
        wpre[t] = s;
    }
    __syncthreads();

    unsigned lmask = (1u << lane) - 1u;
    if (f0) {
        int rank = wpre[warp] + __popc(b0 & lmask);
        int flatc = c * MAXOUT + rank;
        g_cand[flatc] = ((k0 >> 32) << 32) | (unsigned)(0xFFFFFFFFu - (unsigned)flatc);
        ((float4*)g_cand_box)[flatc] = bbox[t];
    }
    if (f1) {
        int rank = wpre[32 + warp] + __popc(b1 & lmask);
        int flatc = c * MAXOUT + rank;
        g_cand[flatc] = ((k1 >> 32) << 32) | (unsigned)(0xFFFFFFFFu - (unsigned)flatc);
        ((float4*)g_cand_box)[flatc] = bbox[p1];
    }
    if (t == 0) {
        int total = 0;
        #pragma unroll
        for (int u = 0; u < 64; u++) total += __popc(ballots[u]);
        g_cnt[c] = total;
    }
}

// ---------------------------------------------------------------------------
// Kernel 2: global top-200 via histogram select + exact ranking (dense keys)
// ---------------------------------------------------------------------------
__global__ __launch_bounds__(1024, 1)
void topk_kernel(float* __restrict__ out)
{
    __shared__ ull subkeys[4224];
    __shared__ ull slots[MAXOUT];
    __shared__ int hist[256];
    __shared__ int scnt_s[NCLS];
    __shared__ int s_m, s_bstar;

    const int t = threadIdx.x;

    if (t < 256) hist[t] = 0;
    if (t < MAXOUT) slots[t] = 0ULL;
    if (t < NCLS) scnt_s[t] = g_cnt[t];
    if (t == 0) { s_m = 0; s_bstar = 0; }
    __syncthreads();

    ull myk[5];
    #pragma unroll
    for (int rep = 0; rep < 5; rep++) {
        int i = t + rep * 1024;
        ull key = 0ULL;
        if (i < CAND_CAP) {
            int c = i / MAXOUT;
            int r = i - c * MAXOUT;
            if (r < scnt_s[c]) key = g_cand[i];
        }
        myk[rep] = key;
        if (key) {
            unsigned sb = (unsigned)(key >> 32);
            int bin = (int)((sb - 0x3F000000u) >> 15);
            bin = min(max(bin, 0), 255);
            atomicAdd(&hist[bin], 1);
        }
    }
    __syncthreads();

    if (t < 256) {
        int sum = 0;
        for (int b = t; b < 256; b++) sum += hist[b];
        if (sum >= MAXOUT) atomicMax(&s_bstar, t);
    }
    __syncthreads();
    int bstar = s_bstar;

    #pragma unroll
    for (int rep = 0; rep < 5; rep++) {
        ull key = myk[rep];
        if (key) {
            unsigned sb = (unsigned)(key >> 32);
            int bin = (int)((sb - 0x3F000000u) >> 15);
            bin = min(max(bin, 0), 255);
            if (bin >= bstar) {
                int pos = atomicAdd(&s_m, 1);
                subkeys[pos] = key;
            }
        }
    }
    __syncthreads();
    int M = s_m;

    for (int s = t; s < M; s += 1024) {
        ull k = subkeys[s];
        int r = 0;
        for (int m = 0; m < M; m++)
            r += (subkeys[m] > k) ? 1 : 0;
        if (r < MAXOUT) slots[r] = k;
    }
    __syncthreads();

    if (t < MAXOUT) {
        float b0 = 0.f, b1 = 0.f, b2 = 0.f, b3 = 0.f, lab = 0.f, sc = 0.f;
        ull key = slots[t];
        if (key != 0ULL) {
            sc = __uint_as_float((unsigned)(key >> 32));
            unsigned flatc = 0xFFFFFFFFu - (unsigned)(key & 0xFFFFFFFFu);
            lab = (float)(flatc / MAXOUT);
            float4 bb = ((const float4*)g_cand_box)[flatc];
            b0 = fminf(fmaxf(bb.x, 0.f), 1.f);
            b1 = fminf(fmaxf(bb.y, 0.f), 1.f);
            b2 = fminf(fmaxf(bb.z, 0.f), 1.f);
            b3 = fminf(fmaxf(bb.w, 0.f), 1.f);
        } else if (t == 0 && M == 0) {
            ull best = 0ULL;
            #pragma unroll
            for (int c2 = 0; c2 < NCLS; c2++) {
                ull v = g_best[c2];
                if (v > best) best = v;
            }
            float s = __uint_as_float((unsigned)(best >> 32));
            if (s >= 0.001f) {
                sc = s;
                int c2 = (int)(0xFFFFFFFFu - (unsigned)(best & 0xFFFFFFFFu));
                lab = (float)c2;
                float4 bb = ((const float4*)g_best_box)[c2];
                b0 = fminf(fmaxf(bb.x, 0.f), 1.f);
                b1 = fminf(fmaxf(bb.y, 0.f), 1.f);
                b2 = fminf(fmaxf(bb.z, 0.f), 1.f);
                b3 = fminf(fmaxf(bb.w, 0.f), 1.f);
            }
        }
        out[t * 4 + 0] = b0;
        out[t * 4 + 1] = b1;
        out[t * 4 + 2] = b2;
        out[t * 4 + 3] = b3;
        out[MAXOUT * 4 + t] = lab;
        out[MAXOUT * 5 + t] = sc;
    }
}

extern "C" void kernel_launch(void* const* d_in, const int* in_sizes, int n_in,
                              void* d_out, int out_size)
{
    (void)in_sizes; (void)n_in; (void)out_size;
    const float* rois   = (const float*)d_in[0];
    const float* deltas = (const float*)d_in[1];
    const float* probs  = (const float*)d_in[2];
    float* out = (float*)d_out;

    score_kernel<<<NANCH / 128, 128>>>(probs);
    class_nms_kernel<<<NCLS, 1024>>>(rois, deltas);
    topk_kernel<<<1, 1024>>>(out);
}